// round 9
// baseline (speedup 1.0000x reference)
#include <cuda_runtime.h>
#include <cuda_bf16.h>
#include <cstddef>

// Problem constants (fixed by the reference):
//   B=64, NTH=56, NTW=56  -> T = 200704 tiles; 4 threads (a "quad") per tile.
//   M = 8 slots/tile, DF = 8 flux fields, D = 2 + DF + 1 = 11 output fields
static constexpr float FAR_SENTINEL = 100.0f;

__device__ __forceinline__ unsigned int nib(unsigned int w, int i) {
    return (w >> (4 * i)) & 0xFu;
}

// ---- packed f32x2 helpers (sm_103a; ptxas won't auto-fuse, PTX required) ----
__device__ __forceinline__ unsigned long long pack2(float lo, float hi) {
    unsigned long long r;
    asm("mov.b64 %0, {%1, %2};" : "=l"(r) : "f"(lo), "f"(hi));
    return r;
}
__device__ __forceinline__ void unpack2(unsigned long long v, float& lo, float& hi) {
    asm("mov.b64 {%0, %1}, %2;" : "=f"(lo), "=f"(hi) : "l"(v));
}
__device__ __forceinline__ unsigned long long add2(unsigned long long a, unsigned long long b) {
    unsigned long long r;
    asm("add.rn.f32x2 %0, %1, %2;" : "=l"(r) : "l"(a), "l"(b));
    return r;
}
__device__ __forceinline__ unsigned long long mul2(unsigned long long a, unsigned long long b) {
    unsigned long long r;
    asm("mul.rn.f32x2 %0, %1, %2;" : "=l"(r) : "l"(a), "l"(b));
    return r;
}

__global__ __launch_bounds__(256, 5) void match_scatter_kernel(
    const float* __restrict__ est_locs,    // [T, 8, 2]
    const float* __restrict__ true_locs,   // [T, 8, 2]
    const float* __restrict__ true_fluxes, // [T, 8, 8]
    const int*   __restrict__ est_ns,      // [T]
    const int*   __restrict__ true_ns,     // [T]
    float*       __restrict__ out,         // [T, 8, 11]
    int T)
{
    const int g   = blockIdx.x * blockDim.x + threadIdx.x;
    const int t   = g >> 2;               // tile
    const int l   = g & 3;                // quad lane: est rows 2l,2l+1; s = 2l,2l+1
    const bool live = (t < T);
    const int tc  = live ? t : (T - 1);   // clamp for safe loads; shfls stay uniform

    const int n_e = est_ns[tc];
    const int n_t = true_ns[tc];

    // ---- true locs: negated + masked, packed as (-x,-y) pairs ----
    // dist uses rn(ex + (-tx)) == rn(ex - tx) exactly (negation is exact).
    const unsigned long long negfar2 = pack2(-FAR_SENTINEL, -FAR_SENTINEL);
    unsigned long long ntl2[8];
    {
        const float4* tp = reinterpret_cast<const float4*>(true_locs) + (size_t)tc * 4;
        #pragma unroll
        for (int i = 0; i < 4; ++i) {
            float4 v = tp[i];
            ntl2[2*i]   = (2*i   < n_t) ? pack2(-v.x, -v.y) : negfar2;
            ntl2[2*i+1] = (2*i+1 < n_t) ? pack2(-v.z, -v.w) : negfar2;
        }
    }

    // ---- this lane's 2 est rows: 8x2 distance sub-block, exact sqrt ----
    float colmin[8];
    int   colarg[8];                  // partial match1 over this lane's rows
    unsigned int m2own = 0u;          // match2 nibbles at GLOBAL row positions

    {
        // one float4 = this lane's two est points; consecutive lanes -> consecutive 16B
        const float4 e = reinterpret_cast<const float4*>(est_locs)[(size_t)tc * 4 + l];
        const unsigned long long far2 = pack2(FAR_SENTINEL, FAR_SENTINEL);
        #pragma unroll
        for (int hh = 0; hh < 2; ++hh) {
            const int  ri   = 2*l + hh;           // global est row
            const bool e_on = ri < n_e;
            const unsigned long long e2 =
                e_on ? (hh ? pack2(e.z, e.w) : pack2(e.x, e.y)) : far2;

            float rmin; int rarg;
            #pragma unroll
            for (int s = 0; s < 8; ++s) {
                const unsigned long long dxy = add2(e2, ntl2[s]);   // (dx, dy), rn each
                const unsigned long long sq  = mul2(dxy, dxy);      // (dx^2, dy^2), rn each
                float s0, s1; unpack2(sq, s0, s1);
                // unfused sum + correctly-rounded sqrt: bit-matches reference ordering
                const float d = __fsqrt_rn(__fadd_rn(s0, s1));
                if (s == 0) { rmin = d; rarg = 0; }                 // peeled seed
                else if (d < rmin) { rmin = d; rarg = s; }          // strict <: first index
                if (hh == 0) { colmin[s] = d; colarg[s] = ri; }     // peeled first row
                else if (d < colmin[s]) { colmin[s] = d; colarg[s] = ri; }
            }
            m2own |= (unsigned int)rarg << (4 * ri);
        }
    }

    // ---- merge column argmins across the quad (lower global row wins ties).
    //      Each round merges disjoint ORDERED row ranges, so "lower group wins
    //      on equal distance" == reference first-occurrence argmin. ----
    #pragma unroll
    for (int m = 1; m <= 2; m <<= 1) {
        const bool partner_lower = (l & m) != 0;
        #pragma unroll
        for (int s = 0; s < 8; ++s) {
            const float ov = __shfl_xor_sync(0xffffffffu, colmin[s], m);
            const int   oa = __shfl_xor_sync(0xffffffffu, colarg[s], m);
            const bool take = (ov < colmin[s]) | ((ov == colmin[s]) & partner_lower);
            colmin[s] = take ? ov : colmin[s];
            colarg[s] = take ? oa : colarg[s];
        }
    }

    // full match2 nibble word (disjoint nibbles -> OR-reduce)
    unsigned int m2full = m2own;
    m2full |= __shfl_xor_sync(0xffffffffu, m2full, 1);
    m2full |= __shfl_xor_sync(0xffffffffu, m2full, 2);

    // pack full match1 nibbles (merged colarg, identical on all quad lanes)
    unsigned int m1pack = 0u;
    #pragma unroll
    for (int j = 0; j < 8; ++j)
        m1pack |= (unsigned int)colarg[j] << (4 * j);

    // ---- one-to-one + scatter for THIS lane's 2 s values (ascending s) ----
    // ok[s]: match1[match2[s]]==s && match1[s] < n_e && match2[s] < n_t
    unsigned int spack = 0x88888888u;
    #pragma unroll
    for (int sl = 0; sl < 2; ++sl) {
        const int s    = 2*l + sl;
        const int m2   = (int)((m2full >> (4 * s)) & 0xFu);
        const int m1c2 = (int)((m1pack >> (4 * m2)) & 0xFu);
        const int c1   = (int)((m1pack >> (4 * s)) & 0xFu);   // match1[s]
        const bool ok  = (m1c2 == s) && (c1 < n_e) && (m2 < n_t);
        if (ok) {
            const int sh = c1 * 4;
            spack = (spack & ~(0xFu << sh)) | ((unsigned int)m2 << sh);
        }
    }
    // merge quad spacks: higher-s lane (later reference write) takes priority.
    // nibble==8 <=> bit3 set (values are 0..8) -> cheap mask expansion.
    #pragma unroll
    for (int m = 1; m <= 2; m <<= 1) {
        const unsigned int other = __shfl_xor_sync(0xffffffffu, spack, m);
        const unsigned int hi = (l & m) ? spack : other;   // higher-s lane's word
        const unsigned int lo = (l & m) ? other : spack;
        const unsigned int msk = ((hi & 0x88888888u) >> 3) * 15u; // nibbles where hi==8
        spack = (hi & ~msk) | (lo & msk);
    }

    if (!live || l >= 2) return;   // lanes 0,1 write halves 0,1

    // ---- output: this lane writes slots 4l..4l+3 = 44 floats = 11 float4 ----
    const float4* fp      = reinterpret_cast<const float4*>(true_fluxes) + (size_t)t * 16;
    const float*  tl_base = true_locs + (size_t)t * 16;   // raw locs, L1-hot

    float buf[44];
    #pragma unroll
    for (int k = 0; k < 44; ++k) buf[k] = 0.0f;

    #pragma unroll
    for (int pl = 0; pl < 4; ++pl) {
        const int p  = 4*l + pl;
        const int sp = (int)nib(spack, p);
        if (sp < 8) {
            float* dst = buf + pl * 11;
            dst[0] = tl_base[sp*2 + 0];
            dst[1] = tl_base[sp*2 + 1];
            const float4 f0 = fp[sp*2 + 0];   // 32B-aligned flux row
            const float4 f1 = fp[sp*2 + 1];
            dst[2] = f0.x; dst[3] = f0.y; dst[4] = f0.z; dst[5] = f0.w;
            dst[6] = f1.x; dst[7] = f1.y; dst[8] = f1.z; dst[9] = f1.w;
            dst[10] = 1.0f;                   // matched implies sp < n_t
        }
    }

    float4* op = reinterpret_cast<float4*>(out) + (size_t)t * 22 + l * 11;
    #pragma unroll
    for (int q = 0; q < 11; ++q)
        op[q] = make_float4(buf[4*q + 0], buf[4*q + 1],
                            buf[4*q + 2], buf[4*q + 3]);
}

extern "C" void kernel_launch(void* const* d_in, const int* in_sizes, int n_in,
                              void* d_out, int out_size)
{
    const float* est_locs    = (const float*)d_in[0];
    const float* true_locs   = (const float*)d_in[1];
    const float* true_fluxes = (const float*)d_in[2];
    const int*   est_ns      = (const int*)d_in[3];
    const int*   true_ns     = (const int*)d_in[4];
    float*       out         = (float*)d_out;

    const int T = in_sizes[3];   // number of tiles

    const int threads = 256;
    const long long total = 4LL * T;      // four threads per tile
    const int blocks = (int)((total + threads - 1) / threads);
    match_scatter_kernel<<<blocks, threads>>>(est_locs, true_locs, true_fluxes,
                                              est_ns, true_ns, out, T);
}

// round 10
// speedup vs baseline: 1.0477x; 1.0477x over previous
#include <cuda_runtime.h>
#include <cuda_bf16.h>
#include <cstddef>

// Problem constants (fixed by the reference):
//   B=64, NTH=56, NTW=56  -> T = 200704 tiles; 4 threads (a "quad") per tile.
//   M = 8 slots/tile, DF = 8 flux fields, D = 2 + DF + 1 = 11 output fields
static constexpr float FAR_SENTINEL = 100.0f;

__device__ __forceinline__ unsigned int nib(unsigned int w, int i) {
    return (w >> (4 * i)) & 0xFu;
}

__global__ __launch_bounds__(256, 5) void match_scatter_kernel(
    const float* __restrict__ est_locs,    // [T, 8, 2]
    const float* __restrict__ true_locs,   // [T, 8, 2]
    const float* __restrict__ true_fluxes, // [T, 8, 8]
    const int*   __restrict__ est_ns,      // [T]
    const int*   __restrict__ true_ns,     // [T]
    float*       __restrict__ out,         // [T, 8, 11]
    int T)
{
    const int g   = blockIdx.x * blockDim.x + threadIdx.x;
    const int t   = g >> 2;               // tile
    const int l   = g & 3;                // quad lane: est rows 2l,2l+1; s = 2l,2l+1
    const bool live = (t < T);
    const int tc  = live ? t : (T - 1);   // clamp for safe loads; shfls stay uniform

    const int n_e = est_ns[tc];
    const int n_t = true_ns[tc];

    // ---- true locs: all 8 points, masked to FAR once (quad-broadcast loads) ----
    float tlx[8], tly[8];
    {
        const float4* tp = reinterpret_cast<const float4*>(true_locs) + (size_t)tc * 4;
        #pragma unroll
        for (int i = 0; i < 4; ++i) {
            float4 v = tp[i];
            tlx[2*i]   = v.x; tly[2*i]   = v.y;
            tlx[2*i+1] = v.z; tly[2*i+1] = v.w;
        }
        #pragma unroll
        for (int s = 0; s < 8; ++s) {
            const bool on = s < n_t;
            tlx[s] = on ? tlx[s] : FAR_SENTINEL;
            tly[s] = on ? tly[s] : FAR_SENTINEL;
        }
    }

    // ---- this lane's 2 est rows: 8x2 distance sub-block, exact sqrt ----
    // Column state packed as key = (float_bits(d) << 32) | row.
    // d >= 0 so float bits order as unsigned; unsigned-min == (min d, then min row)
    // == reference first-occurrence argmin. Merge becomes order-independent.
    unsigned long long colkey[8];
    unsigned int m2own = 0u;          // match2 nibbles at GLOBAL row positions

    {
        // one float4 = this lane's two est points; consecutive lanes -> consecutive 16B
        const float4 e = reinterpret_cast<const float4*>(est_locs)[(size_t)tc * 4 + l];
        #pragma unroll
        for (int hh = 0; hh < 2; ++hh) {
            const int  ri   = 2*l + hh;           // global est row
            const bool e_on = ri < n_e;
            const float ex = e_on ? (hh ? e.z : e.x) : FAR_SENTINEL;
            const float ey = e_on ? (hh ? e.w : e.y) : FAR_SENTINEL;
            float rmin; int rarg;
            #pragma unroll
            for (int s = 0; s < 8; ++s) {
                const float dx = __fadd_rn(ex, -tlx[s]);
                const float dy = __fadd_rn(ey, -tly[s]);
                // unfused + correctly-rounded sqrt: bit-matches reference ordering
                const float d = __fsqrt_rn(__fadd_rn(__fmul_rn(dx, dx),
                                                     __fmul_rn(dy, dy)));
                const unsigned long long key =
                    ((unsigned long long)__float_as_uint(d) << 32) | (unsigned int)ri;
                if (s == 0) { rmin = d; rarg = 0; }            // peeled seed
                else if (d < rmin) { rmin = d; rarg = s; }     // strict <: first index
                if (hh == 0) colkey[s] = key;                  // peeled first row
                else if (key < colkey[s]) colkey[s] = key;
            }
            m2own |= (unsigned int)rarg << (4 * ri);
        }
    }

    // ---- merge column keys across the quad: plain unsigned-min butterfly ----
    #pragma unroll
    for (int m = 1; m <= 2; m <<= 1) {
        #pragma unroll
        for (int s = 0; s < 8; ++s) {
            const unsigned long long ok_ = __shfl_xor_sync(0xffffffffu, colkey[s], m);
            if (ok_ < colkey[s]) colkey[s] = ok_;
        }
    }

    // full match2 nibble word (disjoint nibbles -> OR-reduce)
    unsigned int m2full = m2own;
    m2full |= __shfl_xor_sync(0xffffffffu, m2full, 1);
    m2full |= __shfl_xor_sync(0xffffffffu, m2full, 2);

    // pack full match1 nibbles from merged key low words (identical on all lanes)
    unsigned int m1pack = 0u;
    #pragma unroll
    for (int j = 0; j < 8; ++j)
        m1pack |= ((unsigned int)colkey[j] & 0xFu) << (4 * j);

    // ---- one-to-one + scatter for THIS lane's 2 s values (ascending s) ----
    // ok[s]: match1[match2[s]]==s && match1[s] < n_e && match2[s] < n_t
    unsigned int spack = 0x88888888u;
    #pragma unroll
    for (int sl = 0; sl < 2; ++sl) {
        const int s    = 2*l + sl;
        const int m2   = (int)((m2full >> (4 * s)) & 0xFu);
        const int m1c2 = (int)((m1pack >> (4 * m2)) & 0xFu);
        const int c1   = (int)((m1pack >> (4 * s)) & 0xFu);   // match1[s]
        const bool ok  = (m1c2 == s) && (c1 < n_e) && (m2 < n_t);
        if (ok) {
            const int sh = c1 * 4;
            spack = (spack & ~(0xFu << sh)) | ((unsigned int)m2 << sh);
        }
    }
    // merge quad spacks: higher-s lane (later reference write) takes priority.
    // nibble==8 <=> bit3 set (values are 0..8) -> cheap mask expansion.
    #pragma unroll
    for (int m = 1; m <= 2; m <<= 1) {
        const unsigned int other = __shfl_xor_sync(0xffffffffu, spack, m);
        const unsigned int hi = (l & m) ? spack : other;   // higher-s lane's word
        const unsigned int lo = (l & m) ? other : spack;
        const unsigned int msk = ((hi & 0x88888888u) >> 3) * 15u; // nibbles where hi==8
        spack = (hi & ~msk) | (lo & msk);
    }

    if (!live || l >= 2) return;   // lanes 0,1 write halves 0,1

    // ---- output: this lane writes slots 4l..4l+3 = 44 floats = 11 float4 ----
    const float4* fp      = reinterpret_cast<const float4*>(true_fluxes) + (size_t)t * 16;
    const float*  tl_base = true_locs + (size_t)t * 16;   // raw locs, L1-hot

    float buf[44];
    #pragma unroll
    for (int k = 0; k < 44; ++k) buf[k] = 0.0f;

    #pragma unroll
    for (int pl = 0; pl < 4; ++pl) {
        const int p  = 4*l + pl;
        const int sp = (int)nib(spack, p);
        if (sp < 8) {
            float* dst = buf + pl * 11;
            dst[0] = tl_base[sp*2 + 0];
            dst[1] = tl_base[sp*2 + 1];
            const float4 f0 = fp[sp*2 + 0];   // 32B-aligned flux row
            const float4 f1 = fp[sp*2 + 1];
            dst[2] = f0.x; dst[3] = f0.y; dst[4] = f0.z; dst[5] = f0.w;
            dst[6] = f1.x; dst[7] = f1.y; dst[8] = f1.z; dst[9] = f1.w;
            dst[10] = 1.0f;                   // matched implies sp < n_t
        }
    }

    float4* op = reinterpret_cast<float4*>(out) + (size_t)t * 22 + l * 11;
    #pragma unroll
    for (int q = 0; q < 11; ++q)
        op[q] = make_float4(buf[4*q + 0], buf[4*q + 1],
                            buf[4*q + 2], buf[4*q + 3]);
}

extern "C" void kernel_launch(void* const* d_in, const int* in_sizes, int n_in,
                              void* d_out, int out_size)
{
    const float* est_locs    = (const float*)d_in[0];
    const float* true_locs   = (const float*)d_in[1];
    const float* true_fluxes = (const float*)d_in[2];
    const int*   est_ns      = (const int*)d_in[3];
    const int*   true_ns     = (const int*)d_in[4];
    float*       out         = (float*)d_out;

    const int T = in_sizes[3];   // number of tiles

    const int threads = 256;
    const long long total = 4LL * T;      // four threads per tile
    const int blocks = (int)((total + threads - 1) / threads);
    match_scatter_kernel<<<blocks, threads>>>(est_locs, true_locs, true_fluxes,
                                              est_ns, true_ns, out, T);
}